// round 11
// baseline (speedup 1.0000x reference)
#include <cuda_runtime.h>
#include <cuda_fp16.h>
#include <cstdint>

// ---------------- problem constants ----------------
#define BSZ   256
#define CSZ   2048
#define NC    10000
#define LOGITS (256*10000)
#define FEAT_OFF (2*LOGITS)
#define NW_OFF   (2*LOGITS + BSZ*CSZ)

// ---------------- GEMM tiling ----------------
#define BM 64
#define BN 96
#define BK 64
#define NT (CSZ / BK)              // 32 chunks
#define NTHREADS 192               // 6 warps: 2m x 3n

// smem layout (2-stage A16, 2-stage B f32, 2-stage B fp16)
#define A_ST    8192               // 64 rows x 128B fp16
#define BF32_ST 24576              // 96 rows x 256B f32
#define BF16_ST 12288              // 96 rows x 128B fp16
#define A_OFF(s)    ((s) * A_ST)
#define BF32_OFF(s) (2 * A_ST + (s) * BF32_ST)
#define BF16_OFF(s) (2 * A_ST + 2 * BF32_ST + (s) * BF16_ST)
#define SMEM_TOTAL  (2 * A_ST + 2 * BF32_ST + 2 * BF16_ST)   // 90112

#define POOL_BLOCKS 16384

__device__ __half g_A16[(size_t)BSZ * CSZ];   // fp16 pooled features

static __device__ __forceinline__ uint32_t swz(uint32_t off) {
    return off ^ ((off >> 3) & 0x70);
}
static __device__ __forceinline__ uint32_t smem_u32(const void* p) {
    uint32_t a;
    asm("{ .reg .u64 t; cvta.to.shared.u64 t, %1; cvt.u32.u64 %0, t; }" : "=r"(a) : "l"(p));
    return a;
}
static __device__ __forceinline__ void cp16(uint32_t dst, const void* src, uint32_t sz) {
    asm volatile("cp.async.cg.shared.global.L2::128B [%0], [%1], 16, %2;"
                 :: "r"(dst), "l"(src), "r"(sz) : "memory");
}
static __device__ __forceinline__ void ldsm4(uint32_t* r, uint32_t addr) {
    asm volatile("ldmatrix.sync.aligned.m8n8.x4.shared.b16 {%0,%1,%2,%3}, [%4];"
                 : "=r"(r[0]), "=r"(r[1]), "=r"(r[2]), "=r"(r[3]) : "r"(addr));
}
static __device__ __forceinline__ void mma_f16(float* c, const uint32_t* a, const uint32_t* b) {
    asm volatile(
        "mma.sync.aligned.m16n8k16.row.col.f32.f16.f16.f32 "
        "{%0,%1,%2,%3}, {%4,%5,%6,%7}, {%8,%9}, {%0,%1,%2,%3};"
        : "+f"(c[0]), "+f"(c[1]), "+f"(c[2]), "+f"(c[3])
        : "r"(a[0]), "r"(a[1]), "r"(a[2]), "r"(a[3]), "r"(b[0]), "r"(b[1]));
}
static __device__ __forceinline__ uint32_t h2bits(__half2 h) {
    return *reinterpret_cast<uint32_t*>(&h);
}

// ---------------------------------------------------------------------------
// Kernel 1: global average pool only (W conversion eliminated).
// Writes feat f32, A16 fp16, new_weight = 1.0 (exact algebraic collapse).
// ---------------------------------------------------------------------------
__global__ void pool_kernel(const float* __restrict__ f, float* __restrict__ out) {
    float* feat = out + FEAT_OFF;
    float* nw   = out + NW_OFF;
    long gw  = ((long)blockIdx.x * blockDim.x + threadIdx.x) >> 5;
    int lane = threadIdx.x & 31;
    long r0 = gw * 4;
    const float4* p = reinterpret_cast<const float4*>(f) + r0 * 32 + lane;

    float4 v0 = p[0], v1 = p[32], v2 = p[64], v3 = p[96];
    float s0 = (v0.x + v0.y) + (v0.z + v0.w);
    float s1 = (v1.x + v1.y) + (v1.z + v1.w);
    float s2 = (v2.x + v2.y) + (v2.z + v2.w);
    float s3 = (v3.x + v3.y) + (v3.z + v3.w);
    #pragma unroll
    for (int o = 16; o; o >>= 1) {
        s0 += __shfl_xor_sync(0xffffffffu, s0, o);
        s1 += __shfl_xor_sync(0xffffffffu, s1, o);
        s2 += __shfl_xor_sync(0xffffffffu, s2, o);
        s3 += __shfl_xor_sync(0xffffffffu, s3, o);
    }
    if (lane == 0) {
        const float inv = 1.0f / 128.0f;
        float m0 = s0 * inv, m1 = s1 * inv, m2 = s2 * inv, m3 = s3 * inv;
        *reinterpret_cast<float4*>(feat + r0) = make_float4(m0, m1, m2, m3);
        uint2 u = make_uint2(h2bits(__floats2half2_rn(m0, m1)),
                             h2bits(__floats2half2_rn(m2, m3)));
        *reinterpret_cast<uint2*>(g_A16 + r0) = u;
    }
    if (blockIdx.x == 0 && threadIdx.x < BSZ) nw[threadIdx.x] = 1.0f;
}

// ---------------------------------------------------------------------------
// Kernel 2: fp16 GEMM with inline B f32->fp16 conversion.
// A16 fp16 via cp.async; B f32 via cp.async then smem convert to SW128 fp16.
// 64x96 tile, 192 threads, grid 420 (balanced).
// ---------------------------------------------------------------------------
__global__ __launch_bounds__(NTHREADS, 2)
void gemm_mma(const float* __restrict__ W, float* __restrict__ out)
{
    extern __shared__ char smem[];
    const uint32_t sb = smem_u32(smem);

    const int tid  = threadIdx.x;
    const int wid  = tid >> 5, lane = tid & 31;
    const int wm   = wid & 1;
    const int wn   = wid >> 1;
    const int m0   = blockIdx.y * BM;
    const int n0   = blockIdx.x * BN;
    const int gr   = lane >> 2;
    const int gc   = lane & 3;

    float acc[2][4][4];
    #pragma unroll
    for (int i = 0; i < 2; i++)
        #pragma unroll
        for (int j = 0; j < 4; j++)
            #pragma unroll
            for (int q = 0; q < 4; q++) acc[i][j][q] = 0.0f;

    // swizzled ldmatrix offsets (within a stage) per k-step
    uint32_t aoff[2][4], boff[2][4];
    {
        int ar = (lane & 15);
        int as = (lane >> 4);
        int br = (lane & 7) + ((lane & 16) >> 1);
        int bs = (lane >> 3) & 1;
        #pragma unroll
        for (int s = 0; s < 4; s++) {
            #pragma unroll
            for (int mt = 0; mt < 2; mt++)
                aoff[mt][s] = swz((uint32_t)((wm * 32 + mt * 16 + ar) * 128 + (s * 2 + as) * 16));
            #pragma unroll
            for (int np = 0; np < 2; np++)
                boff[np][s] = swz((uint32_t)((wn * 32 + np * 16 + br) * 128 + (s * 2 + bs) * 16));
        }
    }

    auto load_chunk = [&](int t, int stg) {
        const int k0 = t * BK;
        // A16: 512 x 16B segs over 192 threads
        #pragma unroll
        for (int j = 0; j < 3; j++) {
            int idx = tid + NTHREADS * j;
            if (idx < BM * 8) {
                int r = idx >> 3, c = idx & 7;
                cp16(sb + A_OFF(stg) + swz(r * 128 + c * 16),
                     g_A16 + (size_t)(m0 + r) * CSZ + k0 + c * 8, 16);
            }
        }
        // B f32: 96 rows x 16 segs = 1536 x 16B, exact over 192 threads
        #pragma unroll
        for (int j = 0; j < 8; j++) {
            int idx = tid + NTHREADS * j;
            int r = idx >> 4, c = idx & 15;
            int n = n0 + r;
            cp16(sb + BF32_OFF(stg) + (uint32_t)(r * 256 + c * 16),
                 W + (size_t)(n < NC ? n : 0) * CSZ + k0 + c * 4,
                 n < NC ? 16u : 0u);
        }
        asm volatile("cp.async.commit_group;" ::: "memory");
    };

    load_chunk(0, 0);

    for (int t = 0; t < NT; t++) {
        const int stg = t & 1;
        // sync1: everyone done with chunk t-1 compute -> stage (t+1)&1 reusable
        __syncthreads();
        if (t + 1 < NT) {
            load_chunk(t + 1, stg ^ 1);
            asm volatile("cp.async.wait_group 1;" ::: "memory");   // group t done
        } else {
            asm volatile("cp.async.wait_group 0;" ::: "memory");
        }

        // convert B f32 (plain layout) -> B fp16 (SW128 layout), 128B f32/thread
        {
            const char* srcb = smem + BF32_OFF(stg);
            char* dstb = smem + BF16_OFF(stg);
            #pragma unroll
            for (int j = 0; j < 8; j++) {
                uint32_t o = (uint32_t)(tid * 16 + j * 3072);     // f32 byte offset
                float4 v = *reinterpret_cast<const float4*>(srcb + o);
                uint2 u = make_uint2(h2bits(__floats2half2_rn(v.x, v.y)),
                                     h2bits(__floats2half2_rn(v.z, v.w)));
                uint32_t row = o >> 8;                             // 0..95
                uint32_t cb  = (o & 255) >> 1;                     // fp16 col byte
                *reinterpret_cast<uint2*>(dstb + swz(row * 128 + cb)) = u;
            }
        }
        __syncthreads();   // sync2: fp16 tile visible to all warps

        const uint32_t aBase = sb + A_OFF(stg);
        const uint32_t bBase = sb + BF16_OFF(stg);
        #pragma unroll
        for (int s = 0; s < 4; s++) {
            uint32_t af[2][4], bf[2][4];
            ldsm4(af[0], aBase + aoff[0][s]);
            ldsm4(af[1], aBase + aoff[1][s]);
            ldsm4(bf[0], bBase + boff[0][s]);
            ldsm4(bf[1], bBase + boff[1][s]);
            #pragma unroll
            for (int mt = 0; mt < 2; mt++)
                #pragma unroll
                for (int nt = 0; nt < 4; nt++)
                    mma_f16(acc[mt][nt], af[mt], &bf[nt >> 1][(nt & 1) * 2]);
        }
    }

    float* cls  = out;
    float* pred = out + LOGITS;
    #pragma unroll
    for (int mt = 0; mt < 2; mt++) {
        #pragma unroll
        for (int half = 0; half < 2; half++) {
            int m = m0 + wm * 32 + mt * 16 + gr + half * 8;
            long base = (long)m * NC;
            #pragma unroll
            for (int nt = 0; nt < 4; nt++) {
                int n = n0 + wn * 32 + nt * 8 + gc * 2;
                if (n < NC) {
                    float2 v = make_float2(acc[mt][nt][half * 2], acc[mt][nt][half * 2 + 1]);
                    *reinterpret_cast<float2*>(cls  + base + n) = v;
                    *reinterpret_cast<float2*>(pred + base + n) = v;
                }
            }
        }
    }
}

// ---------------------------------------------------------------------------
extern "C" void kernel_launch(void* const* d_in, const int* in_sizes, int n_in,
                              void* d_out, int out_size) {
    const float* features = (const float*)d_in[0];
    // d_in[1] = targets (unused: new_weight collapses to exactly 1.0)
    const float* weight   = (const float*)d_in[2];
    float* out = (float*)d_out;

    pool_kernel<<<POOL_BLOCKS, 256>>>(features, out);

    cudaFuncSetAttribute(gemm_mma, cudaFuncAttributeMaxDynamicSharedMemorySize, SMEM_TOTAL);
    dim3 grid((NC + BN - 1) / BN, BSZ / BM);   // 105 x 4 = 420 CTAs
    gemm_mma<<<grid, NTHREADS, SMEM_TOTAL>>>(weight, out);
}

// round 12
// speedup vs baseline: 1.2296x; 1.2296x over previous
#include <cuda_runtime.h>
#include <cuda_fp16.h>
#include <cstdint>

// ---------------- problem constants ----------------
#define BSZ   256
#define CSZ   2048
#define NC    10000
#define LOGITS (256*10000)
#define FEAT_OFF (2*LOGITS)
#define NW_OFF   (2*LOGITS + BSZ*CSZ)

// ---------------- GEMM tiling (fp16) ----------------
#define BM 64
#define BN 96
#define BK 64
#define NT (CSZ / BK)              // 32 chunks
#define STAGES 3
#define STAGE_B ((BM + BN) * 128)  // 20480
#define B_OFF (BM * 128)
#define SMEM_TOTAL (STAGES * STAGE_B)   // 61440
#define NTHREADS 128               // 4 warps: 2m x 2n, warp tile 32x48

#define POOL_BLOCKS  16384
#define WCONV_BLOCKS 10000         // 2 float4 per thread

__device__ __half g_W16[(size_t)NC * CSZ];
__device__ __half g_A16[(size_t)BSZ * CSZ];

static __device__ __forceinline__ uint32_t swz(uint32_t off) {
    return off ^ ((off >> 3) & 0x70);
}
static __device__ __forceinline__ uint32_t smem_u32(const void* p) {
    uint32_t a;
    asm("{ .reg .u64 t; cvta.to.shared.u64 t, %1; cvt.u32.u64 %0, t; }" : "=r"(a) : "l"(p));
    return a;
}
static __device__ __forceinline__ void cp16(uint32_t dst, const void* src, uint32_t sz) {
    asm volatile("cp.async.cg.shared.global.L2::128B [%0], [%1], 16, %2;"
                 :: "r"(dst), "l"(src), "r"(sz) : "memory");
}
static __device__ __forceinline__ void ldsm4(uint32_t* r, uint32_t addr) {
    asm volatile("ldmatrix.sync.aligned.m8n8.x4.shared.b16 {%0,%1,%2,%3}, [%4];"
                 : "=r"(r[0]), "=r"(r[1]), "=r"(r[2]), "=r"(r[3]) : "r"(addr));
}
static __device__ __forceinline__ void mma_f16(float* c, const uint32_t* a, const uint32_t* b) {
    asm volatile(
        "mma.sync.aligned.m16n8k16.row.col.f32.f16.f16.f32 "
        "{%0,%1,%2,%3}, {%4,%5,%6,%7}, {%8,%9}, {%0,%1,%2,%3};"
        : "+f"(c[0]), "+f"(c[1]), "+f"(c[2]), "+f"(c[3])
        : "r"(a[0]), "r"(a[1]), "r"(a[2]), "r"(a[3]), "r"(b[0]), "r"(b[1]));
}
static __device__ __forceinline__ uint32_t h2bits(__half2 h) {
    return *reinterpret_cast<uint32_t*>(&h);
}

// ---------------------------------------------------------------------------
// Kernel 1 (fused): pool (feat f32 + A16 fp16 + new_weight=1) and W -> fp16.
// wconv half handles 2 float4 per thread for higher MLP.
// ---------------------------------------------------------------------------
__global__ void mem_kernel(const float* __restrict__ f,
                           const float* __restrict__ W,
                           float* __restrict__ out) {
    if (blockIdx.x < POOL_BLOCKS) {
        float* feat = out + FEAT_OFF;
        float* nw   = out + NW_OFF;
        long gw  = ((long)blockIdx.x * blockDim.x + threadIdx.x) >> 5;
        int lane = threadIdx.x & 31;
        long r0 = gw * 4;
        const float4* p = reinterpret_cast<const float4*>(f) + r0 * 32 + lane;

        float4 v0 = p[0], v1 = p[32], v2 = p[64], v3 = p[96];
        float s0 = (v0.x + v0.y) + (v0.z + v0.w);
        float s1 = (v1.x + v1.y) + (v1.z + v1.w);
        float s2 = (v2.x + v2.y) + (v2.z + v2.w);
        float s3 = (v3.x + v3.y) + (v3.z + v3.w);
        #pragma unroll
        for (int o = 16; o; o >>= 1) {
            s0 += __shfl_xor_sync(0xffffffffu, s0, o);
            s1 += __shfl_xor_sync(0xffffffffu, s1, o);
            s2 += __shfl_xor_sync(0xffffffffu, s2, o);
            s3 += __shfl_xor_sync(0xffffffffu, s3, o);
        }
        if (lane == 0) {
            const float inv = 1.0f / 128.0f;
            float m0 = s0 * inv, m1 = s1 * inv, m2 = s2 * inv, m3 = s3 * inv;
            *reinterpret_cast<float4*>(feat + r0) = make_float4(m0, m1, m2, m3);
            uint2 u = make_uint2(h2bits(__floats2half2_rn(m0, m1)),
                                 h2bits(__floats2half2_rn(m2, m3)));
            *reinterpret_cast<uint2*>(g_A16 + r0) = u;
        }
        if (blockIdx.x == 0 && threadIdx.x < BSZ) nw[threadIdx.x] = 1.0f;
    } else {
        const size_t HALF = (size_t)WCONV_BLOCKS * 256;           // 2,560,000 float4
        size_t i = (size_t)(blockIdx.x - POOL_BLOCKS) * blockDim.x + threadIdx.x;
        float4 v0 = reinterpret_cast<const float4*>(W)[i];
        float4 v1 = reinterpret_cast<const float4*>(W)[i + HALF];
        uint2 u0 = make_uint2(h2bits(__floats2half2_rn(v0.x, v0.y)),
                              h2bits(__floats2half2_rn(v0.z, v0.w)));
        uint2 u1 = make_uint2(h2bits(__floats2half2_rn(v1.x, v1.y)),
                              h2bits(__floats2half2_rn(v1.z, v1.w)));
        reinterpret_cast<uint2*>(g_W16)[i]        = u0;
        reinterpret_cast<uint2*>(g_W16)[i + HALF] = u1;
    }
}

// ---------------------------------------------------------------------------
// Kernel 2: fp16 GEMM 64x96 tile, 128 thr (4 warps 2m x 2n, warp tile 32x48),
// 3-stage cp.async, grid 420 (balanced 3 CTAs/SM).
// ---------------------------------------------------------------------------
__global__ __launch_bounds__(NTHREADS, 3)
void gemm_mma(float* __restrict__ out)
{
    extern __shared__ char smem[];
    const uint32_t sb = smem_u32(smem);

    const int tid  = threadIdx.x;
    const int wid  = tid >> 5, lane = tid & 31;
    const int wm   = wid & 1;          // 2 warp rows x 32 m
    const int wn   = wid >> 1;         // 2 warp cols x 48 n
    const int m0   = blockIdx.y * BM;
    const int n0   = blockIdx.x * BN;
    const int gr   = lane >> 2;
    const int gc   = lane & 3;

    float acc[2][6][4];                // [m16 tile][n8 tile][frag]
    #pragma unroll
    for (int i = 0; i < 2; i++)
        #pragma unroll
        for (int j = 0; j < 6; j++)
            #pragma unroll
            for (int q = 0; q < 4; q++) acc[i][j][q] = 0.0f;

    // swizzled ldmatrix offsets per k-step
    uint32_t aoff[2][4], boff[3][4];
    {
        int ar = (lane & 15);
        int as = (lane >> 4);
        int br = (lane & 7) + ((lane & 16) >> 1);
        int bs = (lane >> 3) & 1;
        #pragma unroll
        for (int s = 0; s < 4; s++) {
            #pragma unroll
            for (int mt = 0; mt < 2; mt++)
                aoff[mt][s] = swz((uint32_t)((wm * 32 + mt * 16 + ar) * 128 + (s * 2 + as) * 16));
            #pragma unroll
            for (int np = 0; np < 3; np++)
                boff[np][s] = swz((uint32_t)((wn * 48 + np * 16 + br) * 128 + (s * 2 + bs) * 16));
        }
    }

    auto load_chunk = [&](int t, int stg) {
        const int k0 = t * BK;
        const uint32_t base = sb + stg * STAGE_B;
        #pragma unroll
        for (int j = 0; j < 4; j++) {              // A: 512 x 16B, exact
            int idx = tid + NTHREADS * j;
            int r = idx >> 3, c = idx & 7;
            cp16(base + swz(r * 128 + c * 16),
                 g_A16 + (size_t)(m0 + r) * CSZ + k0 + c * 8, 16);
        }
        #pragma unroll
        for (int j = 0; j < 6; j++) {              // B: 768 x 16B, exact
            int idx = tid + NTHREADS * j;
            int r = idx >> 3, c = idx & 7;
            int n = n0 + r;
            cp16(base + B_OFF + swz(r * 128 + c * 16),
                 g_W16 + (size_t)(n < NC ? n : 0) * CSZ + k0 + c * 8,
                 n < NC ? 16u : 0u);
        }
        asm volatile("cp.async.commit_group;" ::: "memory");
    };

    load_chunk(0, 0);
    load_chunk(1, 1);

    for (int t = 0; t < NT; t++) {
        const int stg = t % STAGES;
        if (t + 1 < NT) asm volatile("cp.async.wait_group 1;" ::: "memory");
        else            asm volatile("cp.async.wait_group 0;" ::: "memory");
        __syncthreads();
        if (t + 2 < NT) load_chunk(t + 2, (t + 2) % STAGES);

        const uint32_t aBase = sb + stg * STAGE_B;
        const uint32_t bBase = aBase + B_OFF;

        #pragma unroll
        for (int s = 0; s < 4; s++) {
            uint32_t af[2][4], bf[3][4];
            ldsm4(af[0], aBase + aoff[0][s]);
            ldsm4(af[1], aBase + aoff[1][s]);
            ldsm4(bf[0], bBase + boff[0][s]);
            ldsm4(bf[1], bBase + boff[1][s]);
            ldsm4(bf[2], bBase + boff[2][s]);
            #pragma unroll
            for (int mt = 0; mt < 2; mt++)
                #pragma unroll
                for (int nt = 0; nt < 6; nt++)
                    mma_f16(acc[mt][nt], af[mt], &bf[nt >> 1][(nt & 1) * 2]);
        }
    }

    float* cls  = out;
    float* pred = out + LOGITS;
    #pragma unroll
    for (int mt = 0; mt < 2; mt++) {
        #pragma unroll
        for (int half = 0; half < 2; half++) {
            int m = m0 + wm * 32 + mt * 16 + gr + half * 8;
            long base = (long)m * NC;
            #pragma unroll
            for (int nt = 0; nt < 6; nt++) {
                int n = n0 + wn * 48 + nt * 8 + gc * 2;
                if (n < NC) {
                    float2 v = make_float2(acc[mt][nt][half * 2], acc[mt][nt][half * 2 + 1]);
                    *reinterpret_cast<float2*>(cls  + base + n) = v;
                    *reinterpret_cast<float2*>(pred + base + n) = v;
                }
            }
        }
    }
}

// ---------------------------------------------------------------------------
extern "C" void kernel_launch(void* const* d_in, const int* in_sizes, int n_in,
                              void* d_out, int out_size) {
    const float* features = (const float*)d_in[0];
    // d_in[1] = targets (unused: new_weight collapses to exactly 1.0)
    const float* weight   = (const float*)d_in[2];
    float* out = (float*)d_out;

    mem_kernel<<<POOL_BLOCKS + WCONV_BLOCKS, 256>>>(features, weight, out);

    cudaFuncSetAttribute(gemm_mma, cudaFuncAttributeMaxDynamicSharedMemorySize, SMEM_TOTAL);
    dim3 grid((NC + BN - 1) / BN, BSZ / BM);   // 105 x 4 = 420 CTAs
    gemm_mma<<<grid, NTHREADS, SMEM_TOTAL>>>(out);
}